// round 4
// baseline (speedup 1.0000x reference)
#include <cuda_runtime.h>
#include <cstdint>

#define B_   4096
#define K_   1024
#define NG   4096    /* 4*H */
#define H_   1024
#define NM   4

#define STAGE_BYTES 16384     /* A 128x64 s8 (8KB) + B 128x64 s8 (8KB) */
#define NSTAGES     4
#define DSM_BYTES   (NSTAGES * STAGE_BYTES)   /* 64 KB */
#define CHUNKS_PER_BRANCH 16
#define TOTAL_CHUNKS      32

// ---- scratch (device globals; no runtime allocation) ----
__device__ signed char g_yA[2][NM][B_][K_];   // 32 MB  bit-plane ints (s8), K-major
__device__ signed char g_Wt[2][NG][K_];       //  8 MB  weight ints, transposed [N][K]
__device__ float       g_part[B_][NG];        // 64 MB  final gates

// ======================= small math helpers =======================
__device__ __forceinline__ float pact_f(float x, float a) {
    float ax = fabsf(x);
    float t  = fabsf(ax - a);
    float s  = (x > 0.f) ? 0.5f : ((x < 0.f) ? -0.5f : 0.f);
    return s * ((ax - t) + a);
}
__device__ __forceinline__ float qr8(float x, float r) {
    float xs = x / r;
    xs = fminf(fmaxf(xs, -0.9921875f), 0.9921875f);
    return (rintf(xs * 128.f) * 0.0078125f) * r;
}
__device__ __forceinline__ float sigmoidf_(float x) { return 1.f / (1.f + expf(-x)); }

// ======================= PTX helpers (sm_80-class only) =======================
__device__ __forceinline__ uint32_t s2u(const void* p) {
    uint32_t a;
    asm("{ .reg .u64 t; cvta.to.shared.u64 t, %1; cvt.u32.u64 %0, t; }" : "=r"(a) : "l"(p));
    return a;
}
__device__ __forceinline__ void cp16(uint32_t dst, const void* src) {
    asm volatile("cp.async.cg.shared.global [%0], [%1], 16;" :: "r"(dst), "l"(src) : "memory");
}
__device__ __forceinline__ void ldsm4(uint32_t addr, uint32_t& r0, uint32_t& r1,
                                      uint32_t& r2, uint32_t& r3) {
    asm volatile("ldmatrix.sync.aligned.m8n8.x4.shared.b16 {%0,%1,%2,%3}, [%4];"
                 : "=r"(r0), "=r"(r1), "=r"(r2), "=r"(r3) : "r"(addr));
}
__device__ __forceinline__ void imma(int* d, const uint32_t* a, const uint32_t* b) {
    asm volatile(
        "mma.sync.aligned.m16n8k32.row.col.s32.s8.s8.s32 "
        "{%0,%1,%2,%3}, {%4,%5,%6,%7}, {%8,%9}, {%0,%1,%2,%3};"
        : "+r"(d[0]), "+r"(d[1]), "+r"(d[2]), "+r"(d[3])
        : "r"(a[0]), "r"(a[1]), "r"(a[2]), "r"(a[3]), "r"(b[0]), "r"(b[1]));
}

// ======================= activation bit-split (s8 planes) =======================
__global__ void quant_acts_kernel(const float* __restrict__ input,
                                  const float* __restrict__ hx,
                                  const float* __restrict__ a1p,
                                  const float* __restrict__ a11p) {
    int idx = blockIdx.x * blockDim.x + threadIdx.x;
    if (idx >= 2 * (B_ * K_ / 4)) return;
    int branch = idx >> 20;               // B_*K_/4 = 2^20
    int r      = idx & ((B_ * K_ / 4) - 1);
    float a = branch ? *a11p : *a1p;
    float4 x4 = ((const float4*)(branch ? hx : input))[r];
    float xs[4] = {x4.x, x4.y, x4.z, x4.w};
    signed char o[NM][4];
#pragma unroll
    for (int j = 0; j < 4; j++) {
        float xv = pact_f(xs[j], a) / a;
        float beta = 1.f;
#pragma unroll
        for (int mq = 0; mq < NM; mq++) {
            float s = xv / beta;
            s = fminf(fmaxf(s, -0.9921875f), 0.9921875f);
            float yi = rintf(s * 128.f);       // exact int in [-127,127]
            xv = xv - (yi * 0.0078125f) * beta;
            o[mq][j] = (signed char)(int)yi;
            beta *= 0.5f;
        }
    }
#pragma unroll
    for (int mq = 0; mq < NM; mq++)
        ((char4*)&g_yA[branch][mq][0][0])[r] = make_char4(o[mq][0], o[mq][1], o[mq][2], o[mq][3]);
}

// ======================= weight quant + transpose (s8) =======================
__global__ void quant_w_kernel(const float* __restrict__ wih,
                               const float* __restrict__ whh) {
    __shared__ float tile[32][33];
    int branch = blockIdx.z;
    const float* w = branch ? whh : wih;
    int n0 = blockIdx.x * 32, k0 = blockIdx.y * 32;
    int tx = threadIdx.x, ty = threadIdx.y;   // 32 x 8
#pragma unroll
    for (int i = 0; i < 4; i++)
        tile[ty + i * 8][tx] = w[(size_t)(k0 + ty + i * 8) * NG + n0 + tx];
    __syncthreads();
#pragma unroll
    for (int i = 0; i < 4; i++) {
        float v = tile[tx][ty + i * 8];
        v = fminf(fmaxf(v, -0.9921875f), 0.9921875f);
        g_Wt[branch][n0 + ty + i * 8][k0 + tx] = (signed char)(int)rintf(v * 128.f);
    }
}

// ======================= int8 IMMA GEMM, both branches fused =======================
// CTA tile: M=128 (4 planes x 32 batch rows), N=128. BK=64. 8 warps: warp = 32(M) x 64(N).
// grid = (NG/128=32, B_/32=128).
__global__ void __launch_bounds__(256, 2) gemm_int8(const float* __restrict__ a1p,
                                                    const float* __restrict__ a11p,
                                                    const float* __restrict__ bih,
                                                    const float* __restrict__ bhh) {
    extern __shared__ __align__(128) char dsm[];
    __shared__ float comb[32 * 132];
    __shared__ float sbias[2][128];

    const int tid  = threadIdx.x;
    const int lane = tid & 31;
    const int warp = tid >> 5;
    const int p    = warp & 3;     // plane (M subgroup)
    const int nh   = warp >> 2;    // n half (0/1 -> 64 cols)
    const int n0   = blockIdx.x * 128;
    const int blk  = blockIdx.y;

    for (int i = tid; i < 32 * 132; i += 256) comb[i] = 0.f;
    if (tid < 128) {
        float v0 = fminf(fmaxf(bih[n0 + tid], -0.9921875f), 0.9921875f);
        sbias[0][tid] = rintf(v0 * 128.f);
        float v1 = fminf(fmaxf(bhh[n0 + tid], -0.9921875f), 0.9921875f);
        sbias[1][tid] = rintf(v1 * 128.f);
    }

    const uint32_t smem = s2u(dsm);

    // ---- cp.async slots: 2 A-chunks + 2 B-chunks of 16B per thread per stage ----
    uint32_t a_src[2], a_dst[2], b_src[2], b_dst[2];
#pragma unroll
    for (int i = 0; i < 2; i++) {
        int id   = tid + 256 * i;
        int arow = id >> 2, ac = id & 3;        // 128 rows x 4 16B-chunks
        int plane = arow >> 5;
        int brow  = blk * 32 + (arow & 31);
        a_src[i] = (uint32_t)((plane * B_ + brow) * K_ + ac * 16);
        a_dst[i] = (uint32_t)(arow * 64 + (((ac ^ (arow >> 1)) & 3) << 4));
        int nrow = id >> 2, bc = id & 3;
        b_src[i] = (uint32_t)((n0 + nrow) * K_ + bc * 16);
        b_dst[i] = (uint32_t)(8192 + nrow * 64 + (((bc ^ (nrow >> 1)) & 3) << 4));
    }
    const char* gA = (const char*)&g_yA[0][0][0][0];
    const char* gB = (const char*)&g_Wt[0][0][0];

    // ---- ldmatrix lane constants ----
    const int m   = lane >> 3;          // which 8x8 matrix this lane addresses
    const int rr  = lane & 7;
    const int am2 = m >> 1;             // A: k-half bit
    const int amr = (m & 1) * 8;        // A: row-half
    uint32_t aoff[2]; int asw[2];
#pragma unroll
    for (int mt = 0; mt < 2; mt++) {
        int rg = p * 32 + mt * 16 + amr + rr;
        aoff[mt] = (uint32_t)(rg * 64);
        asw[mt]  = (rg >> 1) & 3;
    }
    const int bmr = m >> 1;             // B: j-within-pair bit
    const int bmc = m & 1;              // B: k-half bit
    uint32_t boff[4]; int bsw[4];
#pragma unroll
    for (int t = 0; t < 4; t++) {
        int row = nh * 64 + (2 * t + bmr) * 8 + rr;   // FIX: include warp's n-half
        boff[t] = (uint32_t)(8192 + row * 64);
        bsw[t]  = (row >> 1) & 3;
    }

    int acc[2][8][4];
#pragma unroll
    for (int mt = 0; mt < 2; mt++)
#pragma unroll
        for (int j = 0; j < 8; j++)
#pragma unroll
            for (int d = 0; d < 4; d++) acc[mt][j][d] = 0;

    auto load_stage = [&](int c) {
        int br = c >> 4;
        uint32_t k = (uint32_t)(c & 15) * 64;
        uint32_t st = smem + (uint32_t)(c & 3) * STAGE_BYTES;
        const char* A = gA + (size_t)br * (NM * B_ * K_) + k;
        const char* Bp = gB + (size_t)br * (NG * K_) + k;
#pragma unroll
        for (int i = 0; i < 2; i++) {
            cp16(st + a_dst[i], A + a_src[i]);
            cp16(st + b_dst[i], Bp + b_src[i]);
        }
    };

    auto compute_stage = [&](int c) {
        uint32_t st = smem + (uint32_t)(c & 3) * STAGE_BYTES;
#pragma unroll
        for (int s = 0; s < 2; s++) {          // two k32 steps per BK=64
            uint32_t a[2][4];
#pragma unroll
            for (int mt = 0; mt < 2; mt++) {
                uint32_t ck = (uint32_t)(((s * 2 + am2) ^ asw[mt]) & 3) << 4;
                ldsm4(st + aoff[mt] + ck, a[mt][0], a[mt][1], a[mt][2], a[mt][3]);
            }
            uint32_t b[16];
#pragma unroll
            for (int t = 0; t < 4; t++) {
                uint32_t ck = (uint32_t)(((s * 2 + bmc) ^ bsw[t]) & 3) << 4;
                ldsm4(st + boff[t] + ck, b[4 * t], b[4 * t + 1], b[4 * t + 2], b[4 * t + 3]);
            }
#pragma unroll
            for (int mt = 0; mt < 2; mt++)
#pragma unroll
                for (int j = 0; j < 8; j++)
                    imma(acc[mt][j], a[mt], &b[j * 2]);
        }
    };

    auto epilogue = [&](int br) {
        float av = br ? *a11p : *a1p;
        float scale = av * 0.0078125f / (float)(1 << p);
#pragma unroll
        for (int mt = 0; mt < 2; mt++)
#pragma unroll
            for (int j = 0; j < 8; j++) {
                int nb  = nh * 64 + j * 8 + (lane & 3) * 2;
                int row = mt * 16 + (lane >> 2);
#pragma unroll
                for (int d = 0; d < 4; d++) {
                    int nn = nb + (d & 1);
                    int rw = row + (d >> 1) * 8;
                    float t = (float)acc[mt][j][d] * 0.0078125f + sbias[br][nn];
                    float q = fminf(fmaxf(rintf(t), -127.f), 127.f);
                    atomicAdd(&comb[rw * 132 + nn], q * scale);
                }
            }
    };

    // ---- pipeline: 4 stages, 32 chunks (branch = chunk>>4) ----
#pragma unroll
    for (int c = 0; c < NSTAGES - 1; c++) {
        load_stage(c);
        asm volatile("cp.async.commit_group;" ::: "memory");
    }
    for (int c = 0; c < TOTAL_CHUNKS; c++) {
        asm volatile("cp.async.wait_group 2;" ::: "memory");
        __syncthreads();
        if (c + NSTAGES - 1 < TOTAL_CHUNKS) load_stage(c + NSTAGES - 1);
        asm volatile("cp.async.commit_group;" ::: "memory");
        compute_stage(c);
        if (c == CHUNKS_PER_BRANCH - 1) {
            epilogue(0);
#pragma unroll
            for (int mt = 0; mt < 2; mt++)
#pragma unroll
                for (int j = 0; j < 8; j++)
#pragma unroll
                    for (int d = 0; d < 4; d++) acc[mt][j][d] = 0;
        }
    }
    epilogue(1);
    __syncthreads();

    // ---- write final gates ----
    for (int i = tid; i < 32 * 128; i += 256) {
        int r = i >> 7, n = i & 127;
        g_part[blk * 32 + r][n0 + n] = comb[r * 132 + n];
    }
}

// ======================= fused gate / cell elementwise =======================
__global__ void cell_kernel(const float* __restrict__ cx, float* __restrict__ out,
                            const float* a3, const float* a4, const float* a5,
                            const float* a6, const float* a7, const float* a8,
                            const float* a9, const float* a10, const float* a11) {
    int idx = blockIdx.x * blockDim.x + threadIdx.x;
    if (idx >= B_ * H_) return;
    int b = idx >> 10, h = idx & (H_ - 1);
    const float* row = &g_part[b][0];
    float gi = row[h];
    float gj = row[h + H_];
    float gf = row[h + 2 * H_];
    float go = row[h + 3 * H_];
    float v3 = *a3, v4 = *a4, v5 = *a5, v6 = *a6, v7 = *a7;
    float v8 = *a8, v9 = *a9, v10 = *a10, v11 = *a11;

    float fg  = qr8(pact_f(sigmoidf_(gf), v3), v3);
    float ig  = qr8(pact_f(sigmoidf_(gi), v4), v4);
    float act = qr8(pact_f(tanhf(gj),     v5), v5);
    float og  = qr8(pact_f(sigmoidf_(go), v6), v6);
    float gc  = qr8(pact_f(cx[idx] * fg,  v7), v7);
    float ai  = qr8(pact_f(ig * act,      v8), v8);
    float nc  = qr8(pact_f(gc + ai,       v9), v9);
    float ac  = qr8(pact_f(tanhf(nc),     v10), v10);
    float nh  = qr8(pact_f(ac * og,       v11), v11);

    out[idx]           = nh;
    out[B_ * H_ + idx] = nc;
}

// ======================= launch =======================
extern "C" void kernel_launch(void* const* d_in, const int* in_sizes, int n_in,
                              void* d_out, int out_size) {
    const float* input = (const float*)d_in[0];
    const float* hx    = (const float*)d_in[1];
    const float* cx    = (const float*)d_in[2];
    const float* wih   = (const float*)d_in[3];
    const float* whh   = (const float*)d_in[4];
    const float* bih   = (const float*)d_in[5];
    const float* bhh   = (const float*)d_in[6];
    const float* a1    = (const float*)d_in[7];
    const float* a3    = (const float*)d_in[8];
    const float* a4    = (const float*)d_in[9];
    const float* a5    = (const float*)d_in[10];
    const float* a6    = (const float*)d_in[11];
    const float* a7    = (const float*)d_in[12];
    const float* a8    = (const float*)d_in[13];
    const float* a9    = (const float*)d_in[14];
    const float* a10   = (const float*)d_in[15];
    const float* a11   = (const float*)d_in[16];
    float* out = (float*)d_out;

    static int configured = 0;
    if (!configured) {
        cudaFuncSetAttribute(gemm_int8, cudaFuncAttributeMaxDynamicSharedMemorySize,
                             DSM_BYTES);
        configured = 1;
    }

    quant_acts_kernel<<<(2 * (B_ * K_ / 4) + 255) / 256, 256>>>(input, hx, a1, a11);
    quant_w_kernel<<<dim3(NG / 32, K_ / 32, 2), dim3(32, 8)>>>(wih, whh);

    gemm_int8<<<dim3(NG / 128, B_ / 32), 256, DSM_BYTES>>>(a1, a11, bih, bhh);

    cell_kernel<<<(B_ * H_ + 255) / 256, 256>>>(cx, out, a3, a4, a5, a6, a7,
                                                a8, a9, a10, a11);
}